// round 1
// baseline (speedup 1.0000x reference)
#include <cuda_runtime.h>
#include <cuda_bf16.h>

// Scratch (allocation-free: __device__ globals)
// T1/H: [10000, 128] fp32 ; T2: [10000, 512] fp32
__device__ float g_T1[10000 * 128];
__device__ float g_H [10000 * 128];
__device__ float g_T2[10000 * 512];

// Register-blocked SGEMM: C[M,N] = A[M,K] @ B[K,N] (+bias, +relu)
// A, B, C row-major. Requires N % BN == 0, K % BK == 0 (true for all 4 calls),
// M guarded. blockDim.x == (BM/TM)*(BN/TN) == 256.
template <int BM, int BN, int BK, int TM, int TN, bool HAS_BIAS, bool RELU>
__global__ __launch_bounds__(256)
void sgemm_kernel(int M, int N, int K,
                  const float* __restrict__ A,
                  const float* __restrict__ B,
                  const float* __restrict__ bias,
                  float* __restrict__ C)
{
    __shared__ float As[BK][BM];   // A tile transposed: As[k][m]
    __shared__ float Bs[BK][BN];   // B tile: Bs[k][n]

    constexpr int TCOLS = BN / TN;            // threads per tile-row
    const int tid  = threadIdx.x;
    const int tCol = tid % TCOLS;
    const int tRow = tid / TCOLS;

    const int rowBase = blockIdx.y * BM;
    const int colBase = blockIdx.x * BN;

    float acc[TM][TN];
#pragma unroll
    for (int i = 0; i < TM; i++)
#pragma unroll
        for (int j = 0; j < TN; j++)
            acc[i][j] = 0.0f;

    for (int k0 = 0; k0 < K; k0 += BK) {
        // ---- load A tile (BM x BK), transposed into As, zero-fill OOB rows
#pragma unroll
        for (int i = tid; i < BM * BK; i += 256) {
            const int r = i / BK;
            const int c = i % BK;
            const int gr = rowBase + r;
            As[c][r] = (gr < M) ? A[(long long)gr * K + (k0 + c)] : 0.0f;
        }
        // ---- load B tile (BK x BN), coalesced
#pragma unroll
        for (int i = tid; i < BK * BN; i += 256) {
            const int r = i / BN;
            const int c = i % BN;
            Bs[r][c] = B[(long long)(k0 + r) * N + (colBase + c)];
        }
        __syncthreads();

#pragma unroll
        for (int kk = 0; kk < BK; kk++) {
            float regA[TM], regB[TN];
            // vectorized smem reads (TM, TN multiples of 4; offsets 16B-aligned)
            const float4* a4 = reinterpret_cast<const float4*>(&As[kk][tRow * TM]);
#pragma unroll
            for (int i = 0; i < TM / 4; i++) {
                float4 v = a4[i];
                regA[4*i+0] = v.x; regA[4*i+1] = v.y;
                regA[4*i+2] = v.z; regA[4*i+3] = v.w;
            }
            const float4* b4 = reinterpret_cast<const float4*>(&Bs[kk][tCol * TN]);
#pragma unroll
            for (int j = 0; j < TN / 4; j++) {
                float4 v = b4[j];
                regB[4*j+0] = v.x; regB[4*j+1] = v.y;
                regB[4*j+2] = v.z; regB[4*j+3] = v.w;
            }
#pragma unroll
            for (int i = 0; i < TM; i++)
#pragma unroll
                for (int j = 0; j < TN; j++)
                    acc[i][j] = fmaf(regA[i], regB[j], acc[i][j]);
        }
        __syncthreads();
    }

    // ---- epilogue: bias + relu + vectorized store (row-guarded)
#pragma unroll
    for (int i = 0; i < TM; i++) {
        const int gr = rowBase + tRow * TM + i;
        if (gr < M) {
#pragma unroll
            for (int j = 0; j < TN; j += 4) {
                const int gc = colBase + tCol * TN + j;
                float4 v;
                v.x = acc[i][j + 0];
                v.y = acc[i][j + 1];
                v.z = acc[i][j + 2];
                v.w = acc[i][j + 3];
                if (HAS_BIAS) {
                    v.x += bias[gc + 0];
                    v.y += bias[gc + 1];
                    v.z += bias[gc + 2];
                    v.w += bias[gc + 3];
                }
                if (RELU) {
                    v.x = fmaxf(v.x, 0.0f);
                    v.y = fmaxf(v.y, 0.0f);
                    v.z = fmaxf(v.z, 0.0f);
                    v.w = fmaxf(v.w, 0.0f);
                }
                *reinterpret_cast<float4*>(&C[(long long)gr * N + gc]) = v;
            }
        }
    }
}

extern "C" void kernel_launch(void* const* d_in, const int* in_sizes, int n_in,
                              void* d_out, int out_size)
{
    const float* x   = (const float*)d_in[0];  // [N, NFEAT]
    const float* adj = (const float*)d_in[1];  // [N, N]
    const float* W1  = (const float*)d_in[2];  // [NFEAT, NHID]
    const float* b1  = (const float*)d_in[3];  // [NHID]
    const float* W2  = (const float*)d_in[4];  // [NHID, NFEAT]
    const float* b2  = (const float*)d_in[5];  // [NFEAT]
    float* out = (float*)d_out;                // [N, NFEAT]

    const int NHID  = in_sizes[3];             // 128
    const int NFEAT = in_sizes[5];             // 512
    const int Nn    = in_sizes[0] / NFEAT;     // 10000

    float *T1, *H, *T2;
    cudaGetSymbolAddress((void**)&T1, g_T1);
    cudaGetSymbolAddress((void**)&H,  g_H);
    cudaGetSymbolAddress((void**)&T2, g_T2);

    // 1) T1 = x @ W1                    [Nn, NHID], K=NFEAT
    {
        dim3 grid(NHID / 128, (Nn + 63) / 64);
        sgemm_kernel<64, 128, 8, 4, 8, false, false><<<grid, 256>>>(
            Nn, NHID, NFEAT, x, W1, nullptr, T1);
    }
    // 2) H = relu(adj @ T1 + b1)        [Nn, NHID], K=Nn
    {
        dim3 grid(NHID / 128, (Nn + 63) / 64);
        sgemm_kernel<64, 128, 8, 4, 8, true, true><<<grid, 256>>>(
            Nn, NHID, Nn, adj, T1, b1, H);
    }
    // 3) T2 = H @ W2                    [Nn, NFEAT], K=NHID
    {
        dim3 grid(NFEAT / 128, (Nn + 127) / 128);
        sgemm_kernel<128, 128, 8, 8, 8, false, false><<<grid, 256>>>(
            Nn, NFEAT, NHID, H, W2, nullptr, T2);
    }
    // 4) out = adj @ T2 + b2            [Nn, NFEAT], K=Nn
    {
        dim3 grid(NFEAT / 128, (Nn + 127) / 128);
        sgemm_kernel<128, 128, 8, 8, 8, true, false><<<grid, 256>>>(
            Nn, NFEAT, Nn, adj, T2, b2, out);
    }
}

// round 3
// speedup vs baseline: 3.1319x; 3.1319x over previous
#include <cuda_runtime.h>
#include <cuda_bf16.h>
#include <cstdint>

// ---------------- problem constants ----------------
#define NROWS  10000
#define MPAD   10112           // 79 * 128
#define NHID   128
#define NFEAT  512
#define KPAD   10048           // 314 * 32
#define BKC    32
#define NCHUNK (KPAD / BKC)    // 314
#define TILE_BYTES 10240u      // 128 rows * 80B padded stride
#define STAGE_BYTES (4u * TILE_BYTES)   // Ahi, Alo, Bhi, Blo
#define NSTAGES 4
#define TC_SMEM (NSTAGES * STAGE_BYTES) // 163840

// ---------------- scratch (__device__ globals; no allocs) ----------------
__device__ __align__(256) float g_T1[NROWS * NHID];
__device__ __align__(256) float g_H [NROWS * NHID];
__device__ __align__(256) float g_T2[NROWS * NFEAT];
__device__ __align__(256) __nv_bfloat16 g_adj_hi[(size_t)MPAD * KPAD];
__device__ __align__(256) __nv_bfloat16 g_adj_lo[(size_t)MPAD * KPAD];
__device__ __align__(256) __nv_bfloat16 g_T1t_hi[NHID * KPAD];
__device__ __align__(256) __nv_bfloat16 g_T1t_lo[NHID * KPAD];
__device__ __align__(256) __nv_bfloat16 g_T2t_hi[NFEAT * KPAD];
__device__ __align__(256) __nv_bfloat16 g_T2t_lo[NFEAT * KPAD];

// ---------------- PTX helpers (all legal on bare sm_103) ----------------
__device__ __forceinline__ uint32_t smem_u32(const void* p) {
    uint32_t a;
    asm("{ .reg .u64 t; cvta.to.shared.u64 t, %1; cvt.u32.u64 %0, t; }" : "=r"(a) : "l"(p));
    return a;
}
__device__ __forceinline__ void cp_async16(uint32_t dst, const void* src) {
    asm volatile("cp.async.cg.shared.global [%0], [%1], 16;" :: "r"(dst), "l"(src));
}
__device__ __forceinline__ void cp_commit() {
    asm volatile("cp.async.commit_group;" ::: "memory");
}
template <int N>
__device__ __forceinline__ void cp_wait() {
    asm volatile("cp.async.wait_group %0;" :: "n"(N) : "memory");
}
__device__ __forceinline__ void ldsm4(uint32_t* r, uint32_t addr) {
    asm volatile("ldmatrix.sync.aligned.m8n8.x4.shared.b16 {%0,%1,%2,%3}, [%4];"
                 : "=r"(r[0]), "=r"(r[1]), "=r"(r[2]), "=r"(r[3]) : "r"(addr));
}
__device__ __forceinline__ void mma_bf16(float* d, const uint32_t* a,
                                         uint32_t b0, uint32_t b1) {
    asm volatile(
        "mma.sync.aligned.m16n8k16.row.col.f32.bf16.bf16.f32 "
        "{%0,%1,%2,%3}, {%4,%5,%6,%7}, {%8,%9}, {%0,%1,%2,%3};"
        : "+f"(d[0]), "+f"(d[1]), "+f"(d[2]), "+f"(d[3])
        : "r"(a[0]), "r"(a[1]), "r"(a[2]), "r"(a[3]), "r"(b0), "r"(b1));
}

// ---------------- HMMA split-bf16 GEMM ----------------
// C[m][n] = sum_k (Ahi+Alo)[m][k]*(Bhi+Blo)[n][k] + bias[n]   (3-product emulation)
// A: [MPAD, KPAD] bf16 K-major; B: [Ntot, KPAD] bf16 K-major (= B^T of math B)
template <bool RELU>
__global__ __launch_bounds__(256, 1)
void tc_gemm(const __nv_bfloat16* __restrict__ Ahi,
             const __nv_bfloat16* __restrict__ Alo,
             const __nv_bfloat16* __restrict__ Bhi,
             const __nv_bfloat16* __restrict__ Blo,
             const float* __restrict__ bias,
             float* __restrict__ C, int M, int ldC)
{
    extern __shared__ __align__(128) char smem[];
    const uint32_t sbase = smem_u32(smem);
    const int tid  = threadIdx.x;
    const int wid  = tid >> 5;
    const int lane = tid & 31;
    const int wm = wid & 1;           // 2 warp-rows of 64
    const int wn = wid >> 1;          // 4 warp-cols of 32
    const int m0 = blockIdx.y * 128;
    const int n0 = blockIdx.x * 128;

    const char* bases[4] = {
        (const char*)(Ahi + (size_t)m0 * KPAD),
        (const char*)(Alo + (size_t)m0 * KPAD),
        (const char*)(Bhi + (size_t)n0 * KPAD),
        (const char*)(Blo + (size_t)n0 * KPAD)
    };

    auto load_stage = [&](int c) {
        const uint32_t st = sbase + (uint32_t)(c & (NSTAGES - 1)) * STAGE_BYTES;
        const size_t kb = (size_t)c * (BKC * 2);   // byte offset along K
#pragma unroll
        for (int t = 0; t < 4; t++) {
            const char* gb = bases[t] + kb;
            const uint32_t sb_t = st + (uint32_t)t * TILE_BYTES;
#pragma unroll
            for (int i = 0; i < 2; i++) {
                const int idx = tid + i * 256;      // 0..511
                const int r  = idx >> 2;            // 0..127
                const int cc = idx & 3;             // 16B chunk in 64B row
                cp_async16(sb_t + (uint32_t)r * 80u + (uint32_t)cc * 16u,
                           gb + (size_t)r * (KPAD * 2) + cc * 16);
            }
        }
        cp_commit();
    };

    // ldmatrix per-lane offsets: lanes 0-15 -> rows, lanes 16-31 -> k-high chunk
    const uint32_t rL   = lane & 15;
    const uint32_t cAdd = lane >> 4;
    const uint32_t aoff = (uint32_t)(wm * 64 + rL) * 80u + cAdd * 16u;
    const uint32_t boff = (uint32_t)(wn * 32 + rL) * 80u + cAdd * 16u;

    float acc[4][4][4];
#pragma unroll
    for (int i = 0; i < 4; i++)
#pragma unroll
        for (int j = 0; j < 4; j++)
#pragma unroll
            for (int k = 0; k < 4; k++) acc[i][j][k] = 0.0f;

    // prologue
    load_stage(0); load_stage(1); load_stage(2);

    for (int m = 0; m < NCHUNK; m++) {
        if (m + 3 < NCHUNK) load_stage(m + 3);
        const int rem = NCHUNK - 1 - m;
        if (rem >= 3)      cp_wait<3>();
        else if (rem == 2) cp_wait<2>();
        else if (rem == 1) cp_wait<1>();
        else               cp_wait<0>();
        __syncthreads();

        const uint32_t st = sbase + (uint32_t)(m & (NSTAGES - 1)) * STAGE_BYTES;
#pragma unroll
        for (int p = 0; p < 3; p++) {
            // p0: Ahi*Bhi, p1: Ahi*Blo, p2: Alo*Bhi
            const uint32_t aTile = st + (p == 2 ? TILE_BYTES : 0u);
            const uint32_t bTile = st + (p == 1 ? 3u * TILE_BYTES : 2u * TILE_BYTES);
#pragma unroll
            for (int ks = 0; ks < 2; ks++) {
                const uint32_t aA = aTile + aoff + (uint32_t)ks * 32u;
                const uint32_t bA = bTile + boff + (uint32_t)ks * 32u;
                uint32_t B0[4], B1[4];
                ldsm4(B0, bA);
                ldsm4(B1, bA + 16u * 80u);
#pragma unroll
                for (int mt = 0; mt < 4; mt++) {
                    uint32_t A[4];
                    ldsm4(A, aA + (uint32_t)mt * (16u * 80u));
                    mma_bf16(acc[mt][0], A, B0[0], B0[2]);
                    mma_bf16(acc[mt][1], A, B0[1], B0[3]);
                    mma_bf16(acc[mt][2], A, B1[0], B1[2]);
                    mma_bf16(acc[mt][3], A, B1[1], B1[3]);
                }
            }
        }
        __syncthreads();
    }

    // ---- epilogue: bias + relu, write f32 pairs ----
    const int trow  = lane >> 2;
    const int tcol2 = (lane & 3) * 2;
#pragma unroll
    for (int mt = 0; mt < 4; mt++) {
#pragma unroll
        for (int h = 0; h < 2; h++) {
            const int gr = m0 + wm * 64 + mt * 16 + h * 8 + trow;
            if (gr < M) {
#pragma unroll
                for (int nf = 0; nf < 4; nf++) {
                    const int gc = n0 + wn * 32 + nf * 8 + tcol2;
                    float v0 = acc[mt][nf][h * 2 + 0] + bias[gc];
                    float v1 = acc[mt][nf][h * 2 + 1] + bias[gc + 1];
                    if (RELU) { v0 = fmaxf(v0, 0.0f); v1 = fmaxf(v1, 0.0f); }
                    float2 v; v.x = v0; v.y = v1;
                    *reinterpret_cast<float2*>(&C[(size_t)gr * ldC + gc]) = v;
                }
            }
        }
    }
}

// ---------------- adj split: fp32 [NROWS,NROWS] -> bf16 hi/lo [MPAD,KPAD] ----------------
__global__ void split_adj_kernel(const float* __restrict__ adj,
                                 __nv_bfloat16* __restrict__ hi,
                                 __nv_bfloat16* __restrict__ lo)
{
    const long long t = (long long)blockIdx.x * blockDim.x + threadIdx.x;
    const long long total = (long long)MPAD * (KPAD / 4);
    if (t >= total) return;
    const int c4 = (int)(t % (KPAD / 4));
    const int r  = (int)(t / (KPAD / 4));
    const int k  = c4 * 4;
    float4 v = make_float4(0.f, 0.f, 0.f, 0.f);
    if (r < NROWS && k < NROWS)
        v = *reinterpret_cast<const float4*>(adj + (size_t)r * NROWS + k);
    __nv_bfloat16 h0 = __float2bfloat16(v.x), h1 = __float2bfloat16(v.y);
    __nv_bfloat16 h2 = __float2bfloat16(v.z), h3 = __float2bfloat16(v.w);
    __nv_bfloat16 l0 = __float2bfloat16(v.x - __bfloat162float(h0));
    __nv_bfloat16 l1 = __float2bfloat16(v.y - __bfloat162float(h1));
    __nv_bfloat16 l2 = __float2bfloat16(v.z - __bfloat162float(h2));
    __nv_bfloat16 l3 = __float2bfloat16(v.w - __bfloat162float(h3));
    __nv_bfloat162 H01, H23, L01, L23;
    H01.x = h0; H01.y = h1; H23.x = h2; H23.y = h3;
    L01.x = l0; L01.y = l1; L23.x = l2; L23.y = l3;
    __nv_bfloat162* hp = reinterpret_cast<__nv_bfloat162*>(hi + (size_t)r * KPAD + k);
    __nv_bfloat162* lp = reinterpret_cast<__nv_bfloat162*>(lo + (size_t)r * KPAD + k);
    hp[0] = H01; hp[1] = H23;
    lp[0] = L01; lp[1] = L23;
}

// -------- transpose + split: fp32 [R,C] -> bf16 hi/lo [C, KPAD] (zero-padded K) --------
__global__ void tsplit_kernel(const float* __restrict__ in, int R, int C,
                              __nv_bfloat16* __restrict__ hi,
                              __nv_bfloat16* __restrict__ lo)
{
    const long long t = (long long)blockIdx.x * blockDim.x + threadIdx.x;
    const long long total = (long long)C * KPAD;
    if (t >= total) return;
    const int k = (int)(t % KPAD);
    const int c = (int)(t / KPAD);
    const float v = (k < R) ? in[(size_t)k * C + c] : 0.0f;
    const __nv_bfloat16 h = __float2bfloat16(v);
    hi[t] = h;
    lo[t] = __float2bfloat16(v - __bfloat162float(h));
}

// ---------------- SIMT SGEMM (small GEMMs) ----------------
template <int BM, int BN, int BK, int TM, int TN>
__global__ __launch_bounds__(256)
void sgemm_kernel(int M, int N, int K,
                  const float* __restrict__ A,
                  const float* __restrict__ B,
                  float* __restrict__ C)
{
    __shared__ float As[BK][BM];
    __shared__ float Bs[BK][BN];

    constexpr int TCOLS = BN / TN;
    const int tid  = threadIdx.x;
    const int tCol = tid % TCOLS;
    const int tRow = tid / TCOLS;
    const int rowBase = blockIdx.y * BM;
    const int colBase = blockIdx.x * BN;

    float acc[TM][TN];
#pragma unroll
    for (int i = 0; i < TM; i++)
#pragma unroll
        for (int j = 0; j < TN; j++) acc[i][j] = 0.0f;

    for (int k0 = 0; k0 < K; k0 += BK) {
#pragma unroll
        for (int i = tid; i < BM * BK; i += 256) {
            const int r = i / BK, c = i % BK;
            const int gr = rowBase + r;
            As[c][r] = (gr < M) ? A[(size_t)gr * K + (k0 + c)] : 0.0f;
        }
#pragma unroll
        for (int i = tid; i < BK * BN; i += 256) {
            const int r = i / BN, c = i % BN;
            Bs[r][c] = B[(size_t)(k0 + r) * N + (colBase + c)];
        }
        __syncthreads();
#pragma unroll
        for (int kk = 0; kk < BK; kk++) {
            float regA[TM], regB[TN];
            const float4* a4 = reinterpret_cast<const float4*>(&As[kk][tRow * TM]);
#pragma unroll
            for (int i = 0; i < TM / 4; i++) {
                float4 v = a4[i];
                regA[4*i+0] = v.x; regA[4*i+1] = v.y; regA[4*i+2] = v.z; regA[4*i+3] = v.w;
            }
            const float4* b4 = reinterpret_cast<const float4*>(&Bs[kk][tCol * TN]);
#pragma unroll
            for (int j = 0; j < TN / 4; j++) {
                float4 v = b4[j];
                regB[4*j+0] = v.x; regB[4*j+1] = v.y; regB[4*j+2] = v.z; regB[4*j+3] = v.w;
            }
#pragma unroll
            for (int i = 0; i < TM; i++)
#pragma unroll
                for (int j = 0; j < TN; j++)
                    acc[i][j] = fmaf(regA[i], regB[j], acc[i][j]);
        }
        __syncthreads();
    }
#pragma unroll
    for (int i = 0; i < TM; i++) {
        const int gr = rowBase + tRow * TM + i;
        if (gr < M) {
#pragma unroll
            for (int j = 0; j < TN; j += 4) {
                const int gc = colBase + tCol * TN + j;
                float4 v;
                v.x = acc[i][j+0]; v.y = acc[i][j+1]; v.z = acc[i][j+2]; v.w = acc[i][j+3];
                *reinterpret_cast<float4*>(&C[(size_t)gr * N + gc]) = v;
            }
        }
    }
}

// ---------------- launcher ----------------
extern "C" void kernel_launch(void* const* d_in, const int* in_sizes, int n_in,
                              void* d_out, int out_size)
{
    const float* x   = (const float*)d_in[0];
    const float* adj = (const float*)d_in[1];
    const float* W1  = (const float*)d_in[2];
    const float* b1  = (const float*)d_in[3];
    const float* W2  = (const float*)d_in[4];
    const float* b2  = (const float*)d_in[5];
    float* out = (float*)d_out;

    float *T1, *H, *T2;
    __nv_bfloat16 *Ahi, *Alo, *T1hi, *T1lo, *T2hi, *T2lo;
    cudaGetSymbolAddress((void**)&T1,  g_T1);
    cudaGetSymbolAddress((void**)&H,   g_H);
    cudaGetSymbolAddress((void**)&T2,  g_T2);
    cudaGetSymbolAddress((void**)&Ahi, g_adj_hi);
    cudaGetSymbolAddress((void**)&Alo, g_adj_lo);
    cudaGetSymbolAddress((void**)&T1hi, g_T1t_hi);
    cudaGetSymbolAddress((void**)&T1lo, g_T1t_lo);
    cudaGetSymbolAddress((void**)&T2hi, g_T2t_hi);
    cudaGetSymbolAddress((void**)&T2lo, g_T2t_lo);

    cudaFuncSetAttribute(tc_gemm<true>,  cudaFuncAttributeMaxDynamicSharedMemorySize, TC_SMEM);
    cudaFuncSetAttribute(tc_gemm<false>, cudaFuncAttributeMaxDynamicSharedMemorySize, TC_SMEM);

    // adj -> bf16 hi/lo (padded)
    {
        const long long total = (long long)MPAD * (KPAD / 4);
        split_adj_kernel<<<(unsigned)((total + 255) / 256), 256>>>(adj, Ahi, Alo);
    }
    // T1 = x @ W1   [NROWS, NHID]
    sgemm_kernel<64, 128, 8, 4, 8><<<dim3(1, (NROWS + 63) / 64), 256>>>(
        NROWS, NHID, NFEAT, x, W1, T1);
    // T1t split -> [NHID, KPAD]
    tsplit_kernel<<<(NHID * KPAD + 255) / 256, 256>>>(T1, NROWS, NHID, T1hi, T1lo);
    // H = relu(adj @ T1 + b1)
    tc_gemm<true><<<dim3(1, MPAD / 128), 256, TC_SMEM>>>(
        Ahi, Alo, T1hi, T1lo, b1, H, NROWS, NHID);
    // T2 = H @ W2   [NROWS, NFEAT]
    sgemm_kernel<128, 128, 8, 8, 8><<<dim3(NFEAT / 128, (NROWS + 127) / 128), 256>>>(
        NROWS, NFEAT, NHID, H, W2, T2);
    // T2t split -> [NFEAT, KPAD]
    tsplit_kernel<<<(NFEAT * KPAD + 255) / 256, 256>>>(T2, NROWS, NFEAT, T2hi, T2lo);
    // out = adj @ T2 + b2
    tc_gemm<false><<<dim3(NFEAT / 128, MPAD / 128), 256, TC_SMEM>>>(
        Ahi, Alo, T2hi, T2lo, b2, out, NROWS, NFEAT);
}

// round 4
// speedup vs baseline: 3.2577x; 1.0402x over previous
#include <cuda_runtime.h>
#include <cuda_bf16.h>
#include <cstdint>

// ---------------- problem constants ----------------
#define NROWS  10000
#define MPAD   10112           // 79 * 128
#define NHID   128
#define NFEAT  512
#define KPAD   10048           // 157 * 64
#define BKC    64
#define NCHUNK (KPAD / BKC)    // 157
#define SPLITC 79              // gemm2 split-K boundary (chunks)
#define ROW_STRIDE 144u        // 128B data + 16B pad (conflict-free ldsm)
#define TILE_B  (128u * ROW_STRIDE)        // 18432
#define STAGE_B (4u * TILE_B)              // 73728 (Ahi, Alo, Bhi, Blo)
#define NSTAGES 3
#define TC_SMEM (NSTAGES * STAGE_B)        // 221184

// ---------------- scratch (__device__ globals; no allocs) ----------------
__device__ __align__(256) float g_T1[NROWS * NHID];
__device__ __align__(256) float g_H [NROWS * NHID];
__device__ __align__(256) float g_T2[NROWS * NFEAT];
__device__ __align__(256) float g_part[2 * (size_t)MPAD * NHID];   // split-K partials
__device__ __align__(256) __nv_bfloat16 g_adj_hi[(size_t)MPAD * KPAD];
__device__ __align__(256) __nv_bfloat16 g_adj_lo[(size_t)MPAD * KPAD];
__device__ __align__(256) __nv_bfloat16 g_T1t_hi[NHID * KPAD];
__device__ __align__(256) __nv_bfloat16 g_T1t_lo[NHID * KPAD];
__device__ __align__(256) __nv_bfloat16 g_T2t_hi[NFEAT * KPAD];
__device__ __align__(256) __nv_bfloat16 g_T2t_lo[NFEAT * KPAD];

// ---------------- PTX helpers (legal on bare sm_103) ----------------
__device__ __forceinline__ uint32_t smem_u32(const void* p) {
    uint32_t a;
    asm("{ .reg .u64 t; cvta.to.shared.u64 t, %1; cvt.u32.u64 %0, t; }" : "=r"(a) : "l"(p));
    return a;
}
__device__ __forceinline__ void cp_async16(uint32_t dst, const void* src) {
    asm volatile("cp.async.cg.shared.global [%0], [%1], 16;" :: "r"(dst), "l"(src));
}
__device__ __forceinline__ void cp_commit() {
    asm volatile("cp.async.commit_group;" ::: "memory");
}
template <int N>
__device__ __forceinline__ void cp_wait() {
    asm volatile("cp.async.wait_group %0;" :: "n"(N) : "memory");
}
__device__ __forceinline__ void ldsm4(uint32_t* r, uint32_t addr) {
    asm volatile("ldmatrix.sync.aligned.m8n8.x4.shared.b16 {%0,%1,%2,%3}, [%4];"
                 : "=r"(r[0]), "=r"(r[1]), "=r"(r[2]), "=r"(r[3]) : "r"(addr));
}
__device__ __forceinline__ void mma_bf16(float* d, const uint32_t* a,
                                         uint32_t b0, uint32_t b1) {
    asm volatile(
        "mma.sync.aligned.m16n8k16.row.col.f32.bf16.bf16.f32 "
        "{%0,%1,%2,%3}, {%4,%5,%6,%7}, {%8,%9}, {%0,%1,%2,%3};"
        : "+f"(d[0]), "+f"(d[1]), "+f"(d[2]), "+f"(d[3])
        : "r"(a[0]), "r"(a[1]), "r"(a[2]), "r"(a[3]), "r"(b0), "r"(b1));
}

// ---------------- HMMA split-bf16 GEMM ----------------
// C[m][n] = sum_k (Ahi+Alo)[m][k]*(Bhi+Blo)[n][k] (+bias)   3-product emulation
// A: [MPAD, KPAD] bf16 K-major; B: [Ntot, KPAD] bf16 K-major.
// If gridDim.z==2: blockIdx.z selects chunk range [0,SPLITC) / [SPLITC,NCHUNK)
// and output goes to C + z*part_stride (partial sums, no bias).
template <bool BIAS, bool RELU>
__global__ __launch_bounds__(512, 1)
void tc_gemm(const __nv_bfloat16* __restrict__ Ahi,
             const __nv_bfloat16* __restrict__ Alo,
             const __nv_bfloat16* __restrict__ Bhi,
             const __nv_bfloat16* __restrict__ Blo,
             const float* __restrict__ bias,
             float* __restrict__ C, int M, int ldC, size_t part_stride)
{
    extern __shared__ __align__(128) char smem[];
    const uint32_t sbase = smem_u32(smem);
    const int tid  = threadIdx.x;
    const int wid  = tid >> 5;
    const int lane = tid & 31;
    const int wm = wid & 3;            // 4 warp-rows of 32
    const int wn = wid >> 2;           // 4 warp-cols of 32
    const int m0 = blockIdx.y * 128;
    const int n0 = blockIdx.x * 128;

    int cbeg = 0, cend = NCHUNK;
    if (gridDim.z == 2) {
        if (blockIdx.z == 0) { cend = SPLITC; }
        else                 { cbeg = SPLITC; C += part_stride; }
    }

    const char* bases[4] = {
        (const char*)(Ahi + (size_t)m0 * KPAD),
        (const char*)(Alo + (size_t)m0 * KPAD),
        (const char*)(Bhi + (size_t)n0 * KPAD),
        (const char*)(Blo + (size_t)n0 * KPAD)
    };

    auto load_stage = [&](int c) {
        const uint32_t st = sbase + (uint32_t)(c % NSTAGES) * STAGE_B;
        const size_t kb = (size_t)c * (BKC * 2);   // byte offset along K
#pragma unroll
        for (int i = 0; i < 8; i++) {
            const int idx = tid + i * 512;          // 0..4095
            const int t   = idx >> 10;              // tile 0..3
            const int rem = idx & 1023;
            const int r   = rem >> 3;               // row 0..127
            const int cc  = rem & 7;                // 16B chunk in 128B row
            cp_async16(st + (uint32_t)t * TILE_B + (uint32_t)r * ROW_STRIDE + (uint32_t)cc * 16u,
                       bases[t] + kb + (size_t)r * (KPAD * 2) + cc * 16);
        }
        cp_commit();
    };

    // ldmatrix per-lane offsets
    const uint32_t rL   = lane & 15;
    const uint32_t cAdd = lane >> 4;
    const uint32_t aoff = (uint32_t)(wm * 32 + rL) * ROW_STRIDE + cAdd * 16u;
    const uint32_t boff = (uint32_t)(wn * 32 + rL) * ROW_STRIDE + cAdd * 16u;

    float acc[2][4][4];
#pragma unroll
    for (int i = 0; i < 2; i++)
#pragma unroll
        for (int j = 0; j < 4; j++)
#pragma unroll
            for (int k = 0; k < 4; k++) acc[i][j][k] = 0.0f;

    // prologue
    load_stage(cbeg);
    if (cbeg + 1 < cend) load_stage(cbeg + 1);

    for (int c = cbeg; c < cend; c++) {
        if (c + 2 < cend) load_stage(c + 2);
        const int rem = cend - 1 - c;
        if (rem >= 2)      cp_wait<2>();
        else if (rem == 1) cp_wait<1>();
        else               cp_wait<0>();
        __syncthreads();

        const uint32_t st = sbase + (uint32_t)(c % NSTAGES) * STAGE_B;
#pragma unroll
        for (int p = 0; p < 3; p++) {
            // p0: Ahi*Bhi, p1: Ahi*Blo, p2: Alo*Bhi
            const uint32_t aTile = st + (p == 2 ? TILE_B : 0u);
            const uint32_t bTile = st + (p == 1 ? 3u * TILE_B : 2u * TILE_B);
#pragma unroll
            for (int ks = 0; ks < 4; ks++) {
                const uint32_t aA = aTile + aoff + (uint32_t)ks * 32u;
                const uint32_t bA = bTile + boff + (uint32_t)ks * 32u;
                uint32_t B0[4], B1[4];
                ldsm4(B0, bA);
                ldsm4(B1, bA + 16u * ROW_STRIDE);
#pragma unroll
                for (int mt = 0; mt < 2; mt++) {
                    uint32_t A[4];
                    ldsm4(A, aA + (uint32_t)mt * (16u * ROW_STRIDE));
                    mma_bf16(acc[mt][0], A, B0[0], B0[2]);
                    mma_bf16(acc[mt][1], A, B0[1], B0[3]);
                    mma_bf16(acc[mt][2], A, B1[0], B1[2]);
                    mma_bf16(acc[mt][3], A, B1[1], B1[3]);
                }
            }
        }
        __syncthreads();
    }

    // ---- epilogue ----
    const int trow  = lane >> 2;
    const int tcol2 = (lane & 3) * 2;
#pragma unroll
    for (int mt = 0; mt < 2; mt++) {
#pragma unroll
        for (int h = 0; h < 2; h++) {
            const int gr = m0 + wm * 32 + mt * 16 + h * 8 + trow;
            if (gr < M) {
#pragma unroll
                for (int nf = 0; nf < 4; nf++) {
                    const int gc = n0 + wn * 32 + nf * 8 + tcol2;
                    float v0 = acc[mt][nf][h * 2 + 0];
                    float v1 = acc[mt][nf][h * 2 + 1];
                    if (BIAS) { v0 += bias[gc]; v1 += bias[gc + 1]; }
                    if (RELU) { v0 = fmaxf(v0, 0.0f); v1 = fmaxf(v1, 0.0f); }
                    float2 v; v.x = v0; v.y = v1;
                    *reinterpret_cast<float2*>(&C[(size_t)gr * ldC + gc]) = v;
                }
            }
        }
    }
}

// ---------------- split-K reduce + bias + relu for H ----------------
__global__ void reduce_H_kernel(const float* __restrict__ part,
                                const float* __restrict__ b1,
                                float* __restrict__ H)
{
    const int t = blockIdx.x * blockDim.x + threadIdx.x;   // over NROWS*128/4
    if (t >= NROWS * (NHID / 4)) return;
    const int r = t / (NHID / 4);
    const int c = (t % (NHID / 4)) * 4;
    const float4 p0 = *reinterpret_cast<const float4*>(part + (size_t)r * NHID + c);
    const float4 p1 = *reinterpret_cast<const float4*>(part + (size_t)MPAD * NHID + (size_t)r * NHID + c);
    const float4 b  = *reinterpret_cast<const float4*>(b1 + c);
    float4 v;
    v.x = fmaxf(p0.x + p1.x + b.x, 0.0f);
    v.y = fmaxf(p0.y + p1.y + b.y, 0.0f);
    v.z = fmaxf(p0.z + p1.z + b.z, 0.0f);
    v.w = fmaxf(p0.w + p1.w + b.w, 0.0f);
    *reinterpret_cast<float4*>(H + (size_t)r * NHID + c) = v;
}

// ---------------- adj split: fp32 -> bf16 hi/lo [MPAD,KPAD] ----------------
__global__ void split_adj_kernel(const float* __restrict__ adj,
                                 __nv_bfloat16* __restrict__ hi,
                                 __nv_bfloat16* __restrict__ lo)
{
    const long long t = (long long)blockIdx.x * blockDim.x + threadIdx.x;
    const long long total = (long long)MPAD * (KPAD / 4);
    if (t >= total) return;
    const int c4 = (int)(t % (KPAD / 4));
    const int r  = (int)(t / (KPAD / 4));
    const int k  = c4 * 4;
    float4 v = make_float4(0.f, 0.f, 0.f, 0.f);
    if (r < NROWS && k < NROWS)
        v = *reinterpret_cast<const float4*>(adj + (size_t)r * NROWS + k);
    __nv_bfloat16 h0 = __float2bfloat16(v.x), h1 = __float2bfloat16(v.y);
    __nv_bfloat16 h2 = __float2bfloat16(v.z), h3 = __float2bfloat16(v.w);
    __nv_bfloat16 l0 = __float2bfloat16(v.x - __bfloat162float(h0));
    __nv_bfloat16 l1 = __float2bfloat16(v.y - __bfloat162float(h1));
    __nv_bfloat16 l2 = __float2bfloat16(v.z - __bfloat162float(h2));
    __nv_bfloat16 l3 = __float2bfloat16(v.w - __bfloat162float(h3));
    __nv_bfloat162 H01, H23, L01, L23;
    H01.x = h0; H01.y = h1; H23.x = h2; H23.y = h3;
    L01.x = l0; L01.y = l1; L23.x = l2; L23.y = l3;
    __nv_bfloat162* hp = reinterpret_cast<__nv_bfloat162*>(hi + (size_t)r * KPAD + k);
    __nv_bfloat162* lp = reinterpret_cast<__nv_bfloat162*>(lo + (size_t)r * KPAD + k);
    hp[0] = H01; hp[1] = H23;
    lp[0] = L01; lp[1] = L23;
}

// -------- transpose + split: fp32 [R,C] -> bf16 hi/lo [C, KPAD] --------
__global__ void tsplit_kernel(const float* __restrict__ in, int R, int C,
                              __nv_bfloat16* __restrict__ hi,
                              __nv_bfloat16* __restrict__ lo)
{
    const long long t = (long long)blockIdx.x * blockDim.x + threadIdx.x;
    const long long total = (long long)C * KPAD;
    if (t >= total) return;
    const int k = (int)(t % KPAD);
    const int c = (int)(t / KPAD);
    const float v = (k < R) ? in[(size_t)k * C + c] : 0.0f;
    const __nv_bfloat16 h = __float2bfloat16(v);
    hi[t] = h;
    lo[t] = __float2bfloat16(v - __bfloat162float(h));
}

// ---------------- SIMT SGEMM (small GEMMs) ----------------
template <int BM, int BN, int BK, int TM, int TN>
__global__ __launch_bounds__(256)
void sgemm_kernel(int M, int N, int K,
                  const float* __restrict__ A,
                  const float* __restrict__ B,
                  float* __restrict__ C)
{
    __shared__ float As[BK][BM];
    __shared__ float Bs[BK][BN];
    constexpr int TCOLS = BN / TN;
    const int tid  = threadIdx.x;
    const int tCol = tid % TCOLS;
    const int tRow = tid / TCOLS;
    const int rowBase = blockIdx.y * BM;
    const int colBase = blockIdx.x * BN;

    float acc[TM][TN];
#pragma unroll
    for (int i = 0; i < TM; i++)
#pragma unroll
        for (int j = 0; j < TN; j++) acc[i][j] = 0.0f;

    for (int k0 = 0; k0 < K; k0 += BK) {
#pragma unroll
        for (int i = tid; i < BM * BK; i += 256) {
            const int r = i / BK, c = i % BK;
            const int gr = rowBase + r;
            As[c][r] = (gr < M) ? A[(size_t)gr * K + (k0 + c)] : 0.0f;
        }
#pragma unroll
        for (int i = tid; i < BK * BN; i += 256) {
            const int r = i / BN, c = i % BN;
            Bs[r][c] = B[(size_t)(k0 + r) * N + (colBase + c)];
        }
        __syncthreads();
#pragma unroll
        for (int kk = 0; kk < BK; kk++) {
            float regA[TM], regB[TN];
            const float4* a4 = reinterpret_cast<const float4*>(&As[kk][tRow * TM]);
#pragma unroll
            for (int i = 0; i < TM / 4; i++) {
                float4 v = a4[i];
                regA[4*i+0] = v.x; regA[4*i+1] = v.y; regA[4*i+2] = v.z; regA[4*i+3] = v.w;
            }
            const float4* b4 = reinterpret_cast<const float4*>(&Bs[kk][tCol * TN]);
#pragma unroll
            for (int j = 0; j < TN / 4; j++) {
                float4 v = b4[j];
                regB[4*j+0] = v.x; regB[4*j+1] = v.y; regB[4*j+2] = v.z; regB[4*j+3] = v.w;
            }
#pragma unroll
            for (int i = 0; i < TM; i++)
#pragma unroll
                for (int j = 0; j < TN; j++)
                    acc[i][j] = fmaf(regA[i], regB[j], acc[i][j]);
        }
        __syncthreads();
    }
#pragma unroll
    for (int i = 0; i < TM; i++) {
        const int gr = rowBase + tRow * TM + i;
        if (gr < M) {
#pragma unroll
            for (int j = 0; j < TN; j += 4) {
                const int gc = colBase + tCol * TN + j;
                float4 v;
                v.x = acc[i][j+0]; v.y = acc[i][j+1]; v.z = acc[i][j+2]; v.w = acc[i][j+3];
                *reinterpret_cast<float4*>(&C[(size_t)gr * N + gc]) = v;
            }
        }
    }
}

// ---------------- launcher ----------------
extern "C" void kernel_launch(void* const* d_in, const int* in_sizes, int n_in,
                              void* d_out, int out_size)
{
    const float* x   = (const float*)d_in[0];
    const float* adj = (const float*)d_in[1];
    const float* W1  = (const float*)d_in[2];
    const float* b1  = (const float*)d_in[3];
    const float* W2  = (const float*)d_in[4];
    const float* b2  = (const float*)d_in[5];
    float* out = (float*)d_out;

    float *T1, *H, *T2, *part;
    __nv_bfloat16 *Ahi, *Alo, *T1hi, *T1lo, *T2hi, *T2lo;
    cudaGetSymbolAddress((void**)&T1,  g_T1);
    cudaGetSymbolAddress((void**)&H,   g_H);
    cudaGetSymbolAddress((void**)&T2,  g_T2);
    cudaGetSymbolAddress((void**)&part, g_part);
    cudaGetSymbolAddress((void**)&Ahi, g_adj_hi);
    cudaGetSymbolAddress((void**)&Alo, g_adj_lo);
    cudaGetSymbolAddress((void**)&T1hi, g_T1t_hi);
    cudaGetSymbolAddress((void**)&T1lo, g_T1t_lo);
    cudaGetSymbolAddress((void**)&T2hi, g_T2t_hi);
    cudaGetSymbolAddress((void**)&T2lo, g_T2t_lo);

    cudaFuncSetAttribute(tc_gemm<false, false>, cudaFuncAttributeMaxDynamicSharedMemorySize, TC_SMEM);
    cudaFuncSetAttribute(tc_gemm<true,  false>, cudaFuncAttributeMaxDynamicSharedMemorySize, TC_SMEM);

    // adj -> bf16 hi/lo (padded)
    {
        const long long total = (long long)MPAD * (KPAD / 4);
        split_adj_kernel<<<(unsigned)((total + 255) / 256), 256>>>(adj, Ahi, Alo);
    }
    // T1 = x @ W1
    sgemm_kernel<64, 128, 8, 4, 8><<<dim3(1, (NROWS + 63) / 64), 256>>>(
        NROWS, NHID, NFEAT, x, W1, T1);
    // T1t split -> [NHID, KPAD]
    tsplit_kernel<<<(NHID * KPAD + 255) / 256, 256>>>(T1, NROWS, NHID, T1hi, T1lo);
    // gemm2 split-K partials: part[z] = adj @ T1 (chunk range z)
    tc_gemm<false, false><<<dim3(1, MPAD / 128, 2), 512, TC_SMEM>>>(
        Ahi, Alo, T1hi, T1lo, nullptr, part, MPAD, NHID, (size_t)MPAD * NHID);
    // H = relu(part0 + part1 + b1)
    reduce_H_kernel<<<(NROWS * (NHID / 4) + 255) / 256, 256>>>(part, b1, H);
    // T2 = H @ W2
    sgemm_kernel<128, 128, 8, 8, 8><<<dim3(NFEAT / 128, (NROWS + 127) / 128), 256>>>(
        NROWS, NFEAT, NHID, H, W2, T2);
    // T2t split -> [NFEAT, KPAD]
    tsplit_kernel<<<(NFEAT * KPAD + 255) / 256, 256>>>(T2, NROWS, NFEAT, T2hi, T2lo);
    // out = adj @ T2 + b2
    tc_gemm<true, false><<<dim3(NFEAT / 128, MPAD / 128, 1), 512, TC_SMEM>>>(
        Ahi, Alo, T2hi, T2lo, b2, out, NROWS, NFEAT, 0);
}

// round 5
// speedup vs baseline: 4.8941x; 1.5023x over previous
#include <cuda_runtime.h>
#include <cuda_bf16.h>
#include <cstdint>

// ---------------- problem constants ----------------
#define NROWS  10000
#define MPAD   10112           // 79 * 128
#define NHID   128
#define NFEAT  512
#define KPAD   10048           // 157 * 64
#define BKC    64
#define NCHUNK (KPAD / BKC)    // 157
#define TILE_B  16384u         // 128 rows * 128B (swizzled)
#define STAGE_B (4u * TILE_B)  // 65536 (Ahi, Alo, Bhi, Blo)
#define NSTAGES 3
#define TC_SMEM (NSTAGES * STAGE_B)   // 196608

// ---------------- scratch (__device__ globals; no allocs) ----------------
__device__ __align__(256) float g_T1[NROWS * NHID];
__device__ __align__(256) float g_H [NROWS * NHID];
__device__ __align__(256) float g_T2[NROWS * NFEAT];
__device__ __align__(256) float g_part[2 * (size_t)MPAD * NFEAT];   // split-K partials
__device__ __align__(256) __nv_bfloat16 g_adj_hi[(size_t)MPAD * KPAD];
__device__ __align__(256) __nv_bfloat16 g_adj_lo[(size_t)MPAD * KPAD];
__device__ __align__(256) __nv_bfloat16 g_T1t_hi[NHID * KPAD];
__device__ __align__(256) __nv_bfloat16 g_T1t_lo[NHID * KPAD];
__device__ __align__(256) __nv_bfloat16 g_T2t_hi[NFEAT * KPAD];
__device__ __align__(256) __nv_bfloat16 g_T2t_lo[NFEAT * KPAD];

// ---------------- PTX helpers (legal on bare sm_103) ----------------
__device__ __forceinline__ uint32_t smem_u32(const void* p) {
    uint32_t a;
    asm("{ .reg .u64 t; cvta.to.shared.u64 t, %1; cvt.u32.u64 %0, t; }" : "=r"(a) : "l"(p));
    return a;
}
__device__ __forceinline__ uint32_t swz(uint32_t off) {
    return off ^ ((off >> 3) & 0x70);
}
__device__ __forceinline__ void cp_async16(uint32_t dst, const void* src) {
    asm volatile("cp.async.cg.shared.global [%0], [%1], 16;" :: "r"(dst), "l"(src));
}
__device__ __forceinline__ void cp_commit() {
    asm volatile("cp.async.commit_group;" ::: "memory");
}
template <int N>
__device__ __forceinline__ void cp_wait() {
    asm volatile("cp.async.wait_group %0;" :: "n"(N) : "memory");
}
__device__ __forceinline__ void ldsm4(uint32_t* r, uint32_t addr) {
    asm volatile("ldmatrix.sync.aligned.m8n8.x4.shared.b16 {%0,%1,%2,%3}, [%4];"
                 : "=r"(r[0]), "=r"(r[1]), "=r"(r[2]), "=r"(r[3]) : "r"(addr));
}
__device__ __forceinline__ void mma_bf16(float* d, const uint32_t* a,
                                         uint32_t b0, uint32_t b1) {
    asm volatile(
        "mma.sync.aligned.m16n8k16.row.col.f32.bf16.bf16.f32 "
        "{%0,%1,%2,%3}, {%4,%5,%6,%7}, {%8,%9}, {%0,%1,%2,%3};"
        : "+f"(d[0]), "+f"(d[1]), "+f"(d[2]), "+f"(d[3])
        : "r"(a[0]), "r"(a[1]), "r"(a[2]), "r"(a[3]), "r"(b0), "r"(b1));
}

// ---------------- HMMA split-bf16 GEMM (partial sums) ----------------
// part[z][m][n] = sum_{k in range z} (Ahi+Alo)[m][k]*(Bhi+Blo)[n][k]  (3 products)
// A: [MPAD, KPAD] bf16 K-major; B: [Ntot, KPAD] bf16 K-major.
// blockIdx.z / gridDim.z selects the K-chunk range; output at C + z*part_stride.
__global__ __launch_bounds__(512, 1)
void tc_gemm(const __nv_bfloat16* __restrict__ Ahi,
             const __nv_bfloat16* __restrict__ Alo,
             const __nv_bfloat16* __restrict__ Bhi,
             const __nv_bfloat16* __restrict__ Blo,
             float* __restrict__ C, int ldC, size_t part_stride)
{
    extern __shared__ __align__(128) char smem[];
    const uint32_t sbase = smem_u32(smem);
    const int tid  = threadIdx.x;
    const int wid  = tid >> 5;
    const int lane = tid & 31;
    const int wm = wid & 3;            // 4 warp-rows of 32
    const int wn = wid >> 2;           // 4 warp-cols of 32
    const int m0 = blockIdx.y * 128;
    const int n0 = blockIdx.x * 128;

    const int gz = gridDim.z, bz = blockIdx.z;
    const int cbeg = (NCHUNK * bz) / gz;
    const int cend = (NCHUNK * (bz + 1)) / gz;
    C += (size_t)bz * part_stride;

    const char* bases[4] = {
        (const char*)(Ahi + (size_t)m0 * KPAD),
        (const char*)(Alo + (size_t)m0 * KPAD),
        (const char*)(Bhi + (size_t)n0 * KPAD),
        (const char*)(Blo + (size_t)n0 * KPAD)
    };

    auto load_stage = [&](int c) {
        const uint32_t st = sbase + (uint32_t)(c % NSTAGES) * STAGE_B;
        const size_t kb = (size_t)c * (BKC * 2);
#pragma unroll
        for (int i = 0; i < 8; i++) {
            const int idx = tid + i * 512;          // 0..4095
            const int t   = idx >> 10;              // tile 0..3
            const int rem = idx & 1023;
            const int r   = rem >> 3;               // row 0..127
            const int cc  = rem & 7;                // 16B chunk
            cp_async16(st + (uint32_t)t * TILE_B + swz((uint32_t)(r * 128 + cc * 16)),
                       bases[t] + kb + (size_t)r * (KPAD * 2) + cc * 16);
        }
        cp_commit();
    };

    // ldmatrix logical offsets (swizzle applied per-use)
    const uint32_t rL   = lane & 15;
    const uint32_t cAdd = lane >> 4;
    const uint32_t aRow0 = (uint32_t)(wm * 32 + rL);          // mt=0
    const uint32_t bRow0 = (uint32_t)(wn * 32 + rL);          // nh=0
    const uint32_t kOff0 = cAdd * 16u;

    float acc[2][4][4];
#pragma unroll
    for (int i = 0; i < 2; i++)
#pragma unroll
        for (int j = 0; j < 4; j++)
#pragma unroll
            for (int k = 0; k < 4; k++) acc[i][j][k] = 0.0f;

    // prologue
    load_stage(cbeg);
    if (cbeg + 1 < cend) load_stage(cbeg + 1);

    for (int c = cbeg; c < cend; c++) {
        if (c + 1 < cend) cp_wait<1>(); else cp_wait<0>();
        __syncthreads();
        if (c + 2 < cend) load_stage(c + 2);   // overlaps with compute below

        const uint32_t st   = sbase + (uint32_t)(c % NSTAGES) * STAGE_B;
        const uint32_t tAhi = st;
        const uint32_t tAlo = st + TILE_B;
        const uint32_t tBhi = st + 2u * TILE_B;
        const uint32_t tBlo = st + 3u * TILE_B;

#pragma unroll
        for (int ks = 0; ks < 4; ks++) {
            const uint32_t kb = kOff0 + (uint32_t)ks * 32u;
            uint32_t Ah[2][4], Al[2][4], Bh[2][4], Bl[2][4];
#pragma unroll
            for (int mt = 0; mt < 2; mt++) {
                const uint32_t off = (aRow0 + mt * 16u) * 128u + kb;
                ldsm4(Ah[mt], tAhi + swz(off));
                ldsm4(Al[mt], tAlo + swz(off));
            }
#pragma unroll
            for (int nh = 0; nh < 2; nh++) {
                const uint32_t off = (bRow0 + nh * 16u) * 128u + kb;
                ldsm4(Bh[nh], tBhi + swz(off));
                ldsm4(Bl[nh], tBlo + swz(off));
            }
#pragma unroll
            for (int mt = 0; mt < 2; mt++) {
                // hi*hi
                mma_bf16(acc[mt][0], Ah[mt], Bh[0][0], Bh[0][2]);
                mma_bf16(acc[mt][1], Ah[mt], Bh[0][1], Bh[0][3]);
                mma_bf16(acc[mt][2], Ah[mt], Bh[1][0], Bh[1][2]);
                mma_bf16(acc[mt][3], Ah[mt], Bh[1][1], Bh[1][3]);
                // hi*lo
                mma_bf16(acc[mt][0], Ah[mt], Bl[0][0], Bl[0][2]);
                mma_bf16(acc[mt][1], Ah[mt], Bl[0][1], Bl[0][3]);
                mma_bf16(acc[mt][2], Ah[mt], Bl[1][0], Bl[1][2]);
                mma_bf16(acc[mt][3], Ah[mt], Bl[1][1], Bl[1][3]);
                // lo*hi
                mma_bf16(acc[mt][0], Al[mt], Bh[0][0], Bh[0][2]);
                mma_bf16(acc[mt][1], Al[mt], Bh[0][1], Bh[0][3]);
                mma_bf16(acc[mt][2], Al[mt], Bh[1][0], Bh[1][2]);
                mma_bf16(acc[mt][3], Al[mt], Bh[1][1], Bh[1][3]);
            }
        }
    }

    // ---- epilogue: raw partial sums ----
    const int trow  = lane >> 2;
    const int tcol2 = (lane & 3) * 2;
#pragma unroll
    for (int mt = 0; mt < 2; mt++) {
#pragma unroll
        for (int h = 0; h < 2; h++) {
            const int gr = m0 + wm * 32 + mt * 16 + h * 8 + trow;
#pragma unroll
            for (int nf = 0; nf < 4; nf++) {
                const int gc = n0 + wn * 32 + nf * 8 + tcol2;
                float2 v;
                v.x = acc[mt][nf][h * 2 + 0];
                v.y = acc[mt][nf][h * 2 + 1];
                *reinterpret_cast<float2*>(&C[(size_t)gr * ldC + gc]) = v;
            }
        }
    }
}

// ---------------- split-K reduce: out = (sum parts) + bias (, relu) ----------------
template <int NP, bool RELU>
__global__ void reduce_kernel(const float* __restrict__ part, size_t stride,
                              const float* __restrict__ bias,
                              float* __restrict__ out, int rows, int cols)
{
    const int t = blockIdx.x * blockDim.x + threadIdx.x;
    if (t >= rows * (cols / 4)) return;
    const int r = t / (cols / 4);
    const int c = (t % (cols / 4)) * 4;
    float4 s = *reinterpret_cast<const float4*>(bias + c);
#pragma unroll
    for (int p = 0; p < NP; p++) {
        const float4 v = *reinterpret_cast<const float4*>(part + p * stride + (size_t)r * cols + c);
        s.x += v.x; s.y += v.y; s.z += v.z; s.w += v.w;
    }
    if (RELU) {
        s.x = fmaxf(s.x, 0.0f); s.y = fmaxf(s.y, 0.0f);
        s.z = fmaxf(s.z, 0.0f); s.w = fmaxf(s.w, 0.0f);
    }
    *reinterpret_cast<float4*>(out + (size_t)r * cols + c) = s;
}

// ---------------- adj split: fp32 -> bf16 hi/lo [MPAD,KPAD] ----------------
__global__ void split_adj_kernel(const float* __restrict__ adj,
                                 __nv_bfloat16* __restrict__ hi,
                                 __nv_bfloat16* __restrict__ lo)
{
    const long long t = (long long)blockIdx.x * blockDim.x + threadIdx.x;
    const long long total = (long long)MPAD * (KPAD / 4);
    if (t >= total) return;
    const int c4 = (int)(t % (KPAD / 4));
    const int r  = (int)(t / (KPAD / 4));
    const int k  = c4 * 4;
    float4 v = make_float4(0.f, 0.f, 0.f, 0.f);
    if (r < NROWS && k < NROWS)
        v = *reinterpret_cast<const float4*>(adj + (size_t)r * NROWS + k);
    __nv_bfloat16 h0 = __float2bfloat16(v.x), h1 = __float2bfloat16(v.y);
    __nv_bfloat16 h2 = __float2bfloat16(v.z), h3 = __float2bfloat16(v.w);
    __nv_bfloat16 l0 = __float2bfloat16(v.x - __bfloat162float(h0));
    __nv_bfloat16 l1 = __float2bfloat16(v.y - __bfloat162float(h1));
    __nv_bfloat16 l2 = __float2bfloat16(v.z - __bfloat162float(h2));
    __nv_bfloat16 l3 = __float2bfloat16(v.w - __bfloat162float(h3));
    __nv_bfloat162 H01, H23, L01, L23;
    H01.x = h0; H01.y = h1; H23.x = h2; H23.y = h3;
    L01.x = l0; L01.y = l1; L23.x = l2; L23.y = l3;
    __nv_bfloat162* hp = reinterpret_cast<__nv_bfloat162*>(hi + (size_t)r * KPAD + k);
    __nv_bfloat162* lp = reinterpret_cast<__nv_bfloat162*>(lo + (size_t)r * KPAD + k);
    hp[0] = H01; hp[1] = H23;
    lp[0] = L01; lp[1] = L23;
}

// -------- transpose + split: fp32 [R,C] -> bf16 hi/lo [C, KPAD] --------
__global__ void tsplit_kernel(const float* __restrict__ in, int R, int C,
                              __nv_bfloat16* __restrict__ hi,
                              __nv_bfloat16* __restrict__ lo)
{
    const long long t = (long long)blockIdx.x * blockDim.x + threadIdx.x;
    const long long total = (long long)C * KPAD;
    if (t >= total) return;
    const int k = (int)(t % KPAD);
    const int c = (int)(t / KPAD);
    const float v = (k < R) ? in[(size_t)k * C + c] : 0.0f;
    const __nv_bfloat16 h = __float2bfloat16(v);
    hi[t] = h;
    lo[t] = __float2bfloat16(v - __bfloat162float(h));
}

// ---------------- SIMT SGEMM (small GEMMs) ----------------
template <int BM, int BN, int BK, int TM, int TN>
__global__ __launch_bounds__(256)
void sgemm_kernel(int M, int N, int K,
                  const float* __restrict__ A,
                  const float* __restrict__ B,
                  float* __restrict__ C)
{
    __shared__ float As[BK][BM];
    __shared__ float Bs[BK][BN];
    constexpr int TCOLS = BN / TN;
    const int tid  = threadIdx.x;
    const int tCol = tid % TCOLS;
    const int tRow = tid / TCOLS;
    const int rowBase = blockIdx.y * BM;
    const int colBase = blockIdx.x * BN;

    float acc[TM][TN];
#pragma unroll
    for (int i = 0; i < TM; i++)
#pragma unroll
        for (int j = 0; j < TN; j++) acc[i][j] = 0.0f;

    for (int k0 = 0; k0 < K; k0 += BK) {
#pragma unroll
        for (int i = tid; i < BM * BK; i += 256) {
            const int r = i / BK, c = i % BK;
            const int gr = rowBase + r;
            As[c][r] = (gr < M) ? A[(size_t)gr * K + (k0 + c)] : 0.0f;
        }
#pragma unroll
        for (int i = tid; i < BK * BN; i += 256) {
            const int r = i / BN, c = i % BN;
            Bs[r][c] = B[(size_t)(k0 + r) * N + (colBase + c)];
        }
        __syncthreads();
#pragma unroll
        for (int kk = 0; kk < BK; kk++) {
            float regA[TM], regB[TN];
            const float4* a4 = reinterpret_cast<const float4*>(&As[kk][tRow * TM]);
#pragma unroll
            for (int i = 0; i < TM / 4; i++) {
                float4 v = a4[i];
                regA[4*i+0] = v.x; regA[4*i+1] = v.y; regA[4*i+2] = v.z; regA[4*i+3] = v.w;
            }
            const float4* b4 = reinterpret_cast<const float4*>(&Bs[kk][tCol * TN]);
#pragma unroll
            for (int j = 0; j < TN / 4; j++) {
                float4 v = b4[j];
                regB[4*j+0] = v.x; regB[4*j+1] = v.y; regB[4*j+2] = v.z; regB[4*j+3] = v.w;
            }
#pragma unroll
            for (int i = 0; i < TM; i++)
#pragma unroll
                for (int j = 0; j < TN; j++)
                    acc[i][j] = fmaf(regA[i], regB[j], acc[i][j]);
        }
        __syncthreads();
    }
#pragma unroll
    for (int i = 0; i < TM; i++) {
        const int gr = rowBase + tRow * TM + i;
        if (gr < M) {
#pragma unroll
            for (int j = 0; j < TN; j += 4) {
                const int gc = colBase + tCol * TN + j;
                float4 v;
                v.x = acc[i][j+0]; v.y = acc[i][j+1]; v.z = acc[i][j+2]; v.w = acc[i][j+3];
                *reinterpret_cast<float4*>(&C[(size_t)gr * N + gc]) = v;
            }
        }
    }
}

// ---------------- launcher ----------------
extern "C" void kernel_launch(void* const* d_in, const int* in_sizes, int n_in,
                              void* d_out, int out_size)
{
    const float* x   = (const float*)d_in[0];
    const float* adj = (const float*)d_in[1];
    const float* W1  = (const float*)d_in[2];
    const float* b1  = (const float*)d_in[3];
    const float* W2  = (const float*)d_in[4];
    const float* b2  = (const float*)d_in[5];
    float* out = (float*)d_out;

    float *T1, *H, *T2, *part;
    __nv_bfloat16 *Ahi, *Alo, *T1hi, *T1lo, *T2hi, *T2lo;
    cudaGetSymbolAddress((void**)&T1,  g_T1);
    cudaGetSymbolAddress((void**)&H,   g_H);
    cudaGetSymbolAddress((void**)&T2,  g_T2);
    cudaGetSymbolAddress((void**)&part, g_part);
    cudaGetSymbolAddress((void**)&Ahi, g_adj_hi);
    cudaGetSymbolAddress((void**)&Alo, g_adj_lo);
    cudaGetSymbolAddress((void**)&T1hi, g_T1t_hi);
    cudaGetSymbolAddress((void**)&T1lo, g_T1t_lo);
    cudaGetSymbolAddress((void**)&T2hi, g_T2t_hi);
    cudaGetSymbolAddress((void**)&T2lo, g_T2t_lo);

    cudaFuncSetAttribute(tc_gemm, cudaFuncAttributeMaxDynamicSharedMemorySize, TC_SMEM);

    // adj -> bf16 hi/lo (padded)
    {
        const long long total = (long long)MPAD * (KPAD / 4);
        split_adj_kernel<<<(unsigned)((total + 255) / 256), 256>>>(adj, Ahi, Alo);
    }
    // T1 = x @ W1
    sgemm_kernel<64, 128, 8, 4, 8><<<dim3(1, (NROWS + 63) / 64), 256>>>(
        NROWS, NHID, NFEAT, x, W1, T1);
    // T1t split -> [NHID, KPAD]
    tsplit_kernel<<<(NHID * KPAD + 255) / 256, 256>>>(T1, NROWS, NHID, T1hi, T1lo);
    // gemm2 partials (K-split 4): part[z] = adj @ T1 over chunk range z
    tc_gemm<<<dim3(1, MPAD / 128, 4), 512, TC_SMEM>>>(
        Ahi, Alo, T1hi, T1lo, part, NHID, (size_t)MPAD * NHID);
    // H = relu(sum parts + b1)
    reduce_kernel<4, true><<<(NROWS * (NHID / 4) + 255) / 256, 256>>>(
        part, (size_t)MPAD * NHID, b1, H, NROWS, NHID);
    // T2 = H @ W2
    sgemm_kernel<128, 128, 8, 8, 8><<<dim3(NFEAT / 128, (NROWS + 127) / 128), 256>>>(
        NROWS, NFEAT, NHID, H, W2, T2);
    // T2t split -> [NFEAT, KPAD]
    tsplit_kernel<<<(NFEAT * KPAD + 255) / 256, 256>>>(T2, NROWS, NFEAT, T2hi, T2lo);
    // gemm4 partials (K-split 2): part[z] = adj @ T2 over chunk range z
    tc_gemm<<<dim3(NFEAT / 128, MPAD / 128, 2), 512, TC_SMEM>>>(
        Ahi, Alo, T2hi, T2lo, part, NFEAT, (size_t)MPAD * NFEAT);
    // out = sum parts + b2
    reduce_kernel<2, false><<<(NROWS * (NFEAT / 4) + 255) / 256, 256>>>(
        part, (size_t)MPAD * NFEAT, b2, out, NROWS, NFEAT);
}